// round 16
// baseline (speedup 1.0000x reference)
#include <cuda_runtime.h>
#include <cstdint>

#define Hh 200
#define Ww 196
#define Cc 256
#define NCAMS 6
#define SSZ 400
#define NCELLS (SSZ*SSZ)
#define NPTS (Hh*Ww)     // 39200
#define HQ (Hh/4)        // 50
#define NSEG 4           // channel groups
#define CPG (Cc/NSEG)    // 64 channels per group
#define NTHREADS (NCAMS*Ww*NSEG*HQ)     // 235200
#define NBLK_MAIN ((NTHREADS + 255) / 256)  // 919 (last block: 64 idle lanes)
#define NPQ (Ww*HQ)                     // 9800 h-quads
#define NCPT (NCAMS*NPQ)                // 58800 cell tasks
#define NBLK_CELL ((NCPT + 255) / 256)  // 230 producer blocks (FIRST in grid)
#define GRID (NBLK_CELL + NBLK_MAIN)    // 1149 <= 8/SM x 148 SMs = 1184 resident

// Zero-initialized at module load; phase 2 of the kernel restores everything
// to zero before exit, so every launch / graph replay sees zeroed scratch.
__device__ float    g_sum[NCELLS];
__device__ float    g_cnt[NCELLS];
__device__ int      g_cell[NCAMS * NPTS];  // [cam][w*Hh + h] = cell or -1
__device__ unsigned g_done;                // producer-block arrival counter
__device__ unsigned g_bar;                 // grid-barrier arrivals
__device__ unsigned g_bar2;                // phase-2 completion counter

// ONE launch does everything:
//  Blocks 0..229 (producers): projected cell table (mask+bounds folded in,
//    TRANSPOSED for coalesced int4 reads) + per-cell counts; arrive g_done;
//    park at the grid barrier (~5us in).
//  Blocks 230..1148 (consumers): lean stream of td_feats — 32 channels,
//    one-time rendezvous on g_done (satisfied ~15us earlier) + int4 cell
//    prefetch, 32 more channels hiding that load, <=4 predicated sum atomics.
//  Grid barrier (all 1149 blocks resident by launch_bounds(256,8)).
//  Phase 2: divide/add-bias/store output; reset ALL scratch; last block
//    resets the barrier counters.
__global__ void __launch_bounds__(256, 8) fused_all_kernel(
    const float* __restrict__ td, const float* __restrict__ cam,
    const float* __restrict__ lc, const void*  __restrict__ mask,
    const float* __restrict__ wcls, const float* __restrict__ bcls,
    float* __restrict__ out)
{
    if (blockIdx.x < NBLK_CELL) {
        // ---------------- Producer: cell table + counts ----------------
        __shared__ int s_mode;
        // Mask-dtype fingerprint (mask ~90% true) over first 384 bytes:
        //   int32 0/1 : low byte of words sometimes set, upper 3 bytes never
        //   f32 0/1.0 : low byte never, upper bytes sometimes (0x3f800000)
        //   u8 bool   : both populated
        if (threadIdx.x < 32) {
            const unsigned* mw = (const unsigned*)mask;
            unsigned lo = 0, hi = 0;
            #pragma unroll
            for (int k = 0; k < 3; ++k) {
                unsigned v = mw[threadIdx.x + 32 * k];
                lo |= (v & 0xFFu);
                hi |= (v & 0xFFFFFF00u);
            }
            unsigned any_lo = __ballot_sync(0xFFFFFFFF, lo != 0);
            unsigned any_hi = __ballot_sync(0xFFFFFFFF, hi != 0);
            if (threadIdx.x == 0) {
                int mode;
                if (any_lo && any_hi) mode = 1;   // u8 bool
                else if (any_lo)      mode = 0;   // int32
                else                  mode = 2;   // float32
                s_mode = mode;
            }
        }
        __syncthreads();

        int ct = blockIdx.x * blockDim.x + threadIdx.x;
        if (ct < NCPT) {
            int mode = s_mode;
            int hq = ct % HQ;
            int t2 = ct / HQ;
            int w  = t2 % Ww;
            int c  = t2 / Ww;
            int h0 = hq * 4;

            const float* M = cam + c * 16;
            float m00 = __ldg(M + 0), m01 = __ldg(M + 1), m03 = __ldg(M + 3);
            float m10 = __ldg(M + 4), m11 = __ldg(M + 5), m13 = __ldg(M + 7);

            int4 cells;
            int* cl = (int*)&cells;
            #pragma unroll
            for (int k = 0; k < 4; ++k) {
                int n = (h0 + k) * Ww + w;       // ravel order of (H, W)
                float x = __ldg(lc + n);         // row 0 of logits_coordinates
                float y = __ldg(lc + NPTS + n);  // row 1
                bool mv;
                if (mode == 1)      mv = ((const unsigned char*)mask)[n] != 0;
                else if (mode == 0) mv = ((const int*)mask)[n] != 0;
                else                mv = ((const float*)mask)[n] != 0.f;

                float c0 = fmaf(m00, x, fmaf(m01, y, m03));
                float c1 = fmaf(m10, x, fmaf(m11, y, m13));
                // (coord+100)/0.5 == (coord+100)*2 exactly; jnp.round = half-even
                int i0 = (int)rintf((c0 + 100.0f) * 2.0f);
                int i1 = (int)rintf((c1 + 100.0f) * 2.0f);
                int cell = (mv && i0 >= 0 && i0 < SSZ && i1 >= 0 && i1 < SSZ)
                             ? (i0 * SSZ + i1) : -1;
                cl[k] = cell;
                if (cell >= 0) atomicAdd(&g_cnt[cell], 1.0f);  // counts: geometry only
            }
            *(int4*)(g_cell + c * NPTS + w * Hh + h0) = cells; // coalesced
        }
        __syncthreads();
        if (threadIdx.x == 0) {
            __threadfence();                 // publish table + counts
            atomicAdd(&g_done, 1u);
        }
    } else {
        // ---------------- Consumer: lean stream + scatter ----------------
        __shared__ float s_w[Cc];
        for (int i = threadIdx.x; i < Cc; i += blockDim.x) s_w[i] = wcls[i];
        __syncthreads();

        int tid = (blockIdx.x - NBLK_CELL) * blockDim.x + threadIdx.x;
        const bool work = tid < NTHREADS;    // tail lanes stay for barriers
        int t = work ? tid : 0;
        // hq innermost for coalescing, then chan-group, then w, then cam
        int hq  = t % HQ;
        int t2  = t / HQ;
        int seg = t2 % NSEG;
        int t3  = t2 / NSEG;
        int w   = t3 % Ww;
        int c   = t3 / Ww;
        int h0  = hq * 4;
        int ch0 = seg * CPG;

        // td: ((c*C + ch)*W + w)*H + h ; h innermost, 16B aligned (H%4==0)
        const float4* __restrict__ base =
            (const float4*)(td + ((size_t)(c * Cc + ch0) * Ww + w) * Hh + h0);
        const int ch_stride4 = (Ww * Hh) / 4;   // 9800 float4 between channels

        float acc0 = 0.f, acc1 = 0.f, acc2 = 0.f, acc3 = 0.f;

        if (work) {
            #pragma unroll 8
            for (int ch = 0; ch < CPG / 2; ++ch) {
                float4 v = __ldg(base + ch * ch_stride4);
                float wv = s_w[ch0 + ch];
                acc0 = fmaf(v.x, wv, acc0);
                acc1 = fmaf(v.y, wv, acc1);
                acc2 = fmaf(v.z, wv, acc2);
                acc3 = fmaf(v.w, wv, acc3);
            }
        }

        // Rendezvous with producers (satisfied ~15us earlier in steady state).
        if (threadIdx.x == 0) {
            while (*((volatile unsigned*)&g_done) < NBLK_CELL) { __nanosleep(64); }
        }
        __syncthreads();
        __threadfence();   // acquire: table + counts visible

        int4 cells = make_int4(-1, -1, -1, -1);
        if (work) {
            // Prefetch; latency hides under the second half of the stream.
            cells = __ldg((const int4*)(g_cell + c * NPTS + w * Hh + h0));
            #pragma unroll 8
            for (int ch = CPG / 2; ch < CPG; ++ch) {
                float4 v = __ldg(base + ch * ch_stride4);
                float wv = s_w[ch0 + ch];
                acc0 = fmaf(v.x, wv, acc0);
                acc1 = fmaf(v.y, wv, acc1);
                acc2 = fmaf(v.z, wv, acc2);
                acc3 = fmaf(v.w, wv, acc3);
            }

            float accs[4] = {acc0, acc1, acc2, acc3};
            int   cls[4]  = {cells.x, cells.y, cells.z, cells.w};
            #pragma unroll
            for (int k = 0; k < 4; ++k) {
                if (cls[k] >= 0)
                    atomicAdd(&g_sum[cls[k]], accs[k]);  // partial dot; linear so OK
            }
        }
    }

    // ---------------- Grid barrier (all 1149 blocks resident) ----------------
    __threadfence();           // flush this thread's atomics device-wide
    __syncthreads();
    if (threadIdx.x == 0) {
        atomicAdd(&g_bar, 1u);
        while (*((volatile unsigned*)&g_bar) < GRID) { __nanosleep(256); }
    }
    __syncthreads();
    __threadfence();           // acquire: see all blocks' atomics

    // ---------------- Phase 2: finalize + reset scratch ----------------
    {
        int i = blockIdx.x * blockDim.x + threadIdx.x;   // float2 pair index
        if (i == 0) g_done = 0;                          // no one reads it anymore
        if (i < NCELLS / 2) {
            float  b = __ldg(bcls);
            float2 s = ((const float2*)g_sum)[i];
            float2 n = ((const float2*)g_cnt)[i];
            float2 o;
            o.x = s.x / fmaxf(n.x, 1.0f) + b;  // cnt==0 -> sum==0 -> b (matches ref)
            o.y = s.y / fmaxf(n.y, 1.0f) + b;
            ((float2*)out)[i] = o;
            float2 z = make_float2(0.f, 0.f);
            ((float2*)g_sum)[i] = z;
            ((float2*)g_cnt)[i] = z;
        }
    }

    // Last block to finish phase 2 resets the barrier counters for next launch.
    if (threadIdx.x == 0) {
        __threadfence();
        if (atomicAdd(&g_bar2, 1u) + 1 == GRID) {
            g_bar  = 0;
            g_bar2 = 0;
        }
    }
}

extern "C" void kernel_launch(void* const* d_in, const int* in_sizes, int n_in,
                              void* d_out, int out_size) {
    const float* td   = (const float*)d_in[0];  // (1,6,256,196,200) f32
    const float* cam  = (const float*)d_in[1];  // (1,6,4,4) f32
    const float* lc   = (const float*)d_in[2];  // (4,39200) f32
    const void*  mask = (const void*) d_in[3];  // (200,196) bool-ish
    const float* wcls = (const float*)d_in[4];  // (256,) f32
    const float* bcls = (const float*)d_in[5];  // () f32
    float* out = (float*)d_out;                 // (1,1,400,400) f32

    fused_all_kernel<<<GRID, 256>>>(td, cam, lc, mask, wcls, bcls, out);
}

// round 17
// speedup vs baseline: 1.0039x; 1.0039x over previous
#include <cuda_runtime.h>
#include <cstdint>

#define Hh 200
#define Ww 196
#define Cc 256
#define NCAMS 6
#define SSZ 400
#define NCELLS (SSZ*SSZ)
#define NPTS (Hh*Ww)     // 39200
#define HQ (Hh/4)        // 50
#define NSEG 4           // channel groups
#define CPG (Cc/NSEG)    // 64 channels per group
#define NTHREADS (NCAMS*Ww*NSEG*HQ)     // 235200
#define NBLK_MAIN ((NTHREADS + 255) / 256)  // 919 blocks (last: 64 idle lanes)
#define NPQ (Ww*HQ)                     // 9800 h-quads
#define NCPT (NCAMS*NPQ)                // 58800 cell tasks
#define NBLK_CELL ((NCPT + 255) / 256)  // 230 blocks also run the prologue

// Zero-initialized at module load; final_kernel resets sum/cnt/g_done each
// launch so every launch / graph replay sees zeroed scratch. g_cell is fully
// rewritten by the prologue each launch (deterministic).
__device__ float    g_sum[NCELLS];
__device__ float    g_cnt[NCELLS];
__device__ int      g_cell[NCAMS * NPTS];  // [cam][w*Hh + h] = cell or -1
__device__ unsigned g_done;                // prologue-block arrival counter

// 919 blocks, all streaming one tile each; the FIRST 230 additionally run the
// geometry prologue before their tile (no dedicated producer blocks -> no SM
// slots going idle early; worst-SM tile count drops ~8 -> ~7).
//  Prologue (blocks 0..229, ~2us): projected cell table (mask+bounds folded
//    in, TRANSPOSED for coalesced int4 reads) + per-cell counts; arrive g_done.
//  Body (all blocks): 32 channels of td_feats, mid-stream rendezvous on
//    g_done + int4 cell prefetch, 32 more channels hiding that load,
//    <=4 predicated sum atomics.
__global__ void __launch_bounds__(256, 8) fused_dot_scatter_kernel(
    const float* __restrict__ td, const float* __restrict__ cam,
    const float* __restrict__ lc, const void*  __restrict__ mask,
    const float* __restrict__ wcls)
{
    __shared__ float s_w[Cc];
    for (int i = threadIdx.x; i < Cc; i += blockDim.x) s_w[i] = wcls[i];

    // ---------------- Prologue: cell table + counts (blocks 0..229) ----------------
    if (blockIdx.x < NBLK_CELL) {
        __shared__ int s_mode;
        // Mask-dtype fingerprint (mask ~90% true) over first 384 bytes:
        //   int32 0/1 : low byte of words sometimes set, upper 3 bytes never
        //   f32 0/1.0 : low byte never, upper bytes sometimes (0x3f800000)
        //   u8 bool   : both populated
        if (threadIdx.x < 32) {
            const unsigned* mw = (const unsigned*)mask;
            unsigned lo = 0, hi = 0;
            #pragma unroll
            for (int k = 0; k < 3; ++k) {
                unsigned v = mw[threadIdx.x + 32 * k];
                lo |= (v & 0xFFu);
                hi |= (v & 0xFFFFFF00u);
            }
            unsigned any_lo = __ballot_sync(0xFFFFFFFF, lo != 0);
            unsigned any_hi = __ballot_sync(0xFFFFFFFF, hi != 0);
            if (threadIdx.x == 0) {
                int mode;
                if (any_lo && any_hi) mode = 1;   // u8 bool
                else if (any_lo)      mode = 0;   // int32
                else                  mode = 2;   // float32
                s_mode = mode;
            }
        }
        __syncthreads();

        int ct = blockIdx.x * blockDim.x + threadIdx.x;
        if (ct < NCPT) {
            int mode = s_mode;
            int hq = ct % HQ;
            int t2 = ct / HQ;
            int w  = t2 % Ww;
            int c  = t2 / Ww;
            int h0 = hq * 4;

            const float* M = cam + c * 16;
            float m00 = __ldg(M + 0), m01 = __ldg(M + 1), m03 = __ldg(M + 3);
            float m10 = __ldg(M + 4), m11 = __ldg(M + 5), m13 = __ldg(M + 7);

            int4 cells;
            int* cl = (int*)&cells;
            #pragma unroll
            for (int k = 0; k < 4; ++k) {
                int n = (h0 + k) * Ww + w;       // ravel order of (H, W)
                float x = __ldg(lc + n);         // row 0 of logits_coordinates
                float y = __ldg(lc + NPTS + n);  // row 1
                bool mv;
                if (mode == 1)      mv = ((const unsigned char*)mask)[n] != 0;
                else if (mode == 0) mv = ((const int*)mask)[n] != 0;
                else                mv = ((const float*)mask)[n] != 0.f;

                float c0 = fmaf(m00, x, fmaf(m01, y, m03));
                float c1 = fmaf(m10, x, fmaf(m11, y, m13));
                // (coord+100)/0.5 == (coord+100)*2 exactly; jnp.round = half-even
                int i0 = (int)rintf((c0 + 100.0f) * 2.0f);
                int i1 = (int)rintf((c1 + 100.0f) * 2.0f);
                int cell = (mv && i0 >= 0 && i0 < SSZ && i1 >= 0 && i1 < SSZ)
                             ? (i0 * SSZ + i1) : -1;
                cl[k] = cell;
                if (cell >= 0) atomicAdd(&g_cnt[cell], 1.0f);  // counts: geometry only
            }
            *(int4*)(g_cell + c * NPTS + w * Hh + h0) = cells; // coalesced
        }
        __syncthreads();
        if (threadIdx.x == 0) {
            __threadfence();                 // publish table + counts
            atomicAdd(&g_done, 1u);
        }
    } else {
        __syncthreads();                     // s_w visible
    }

    // ---------------- Body: stream one tile + scatter ----------------
    int tid = blockIdx.x * blockDim.x + threadIdx.x;
    const bool work = tid < NTHREADS;        // last block: 64 lanes idle
    int t = work ? tid : 0;
    // hq innermost for coalescing, then chan-group, then w, then cam
    int hq  = t % HQ;
    int t2  = t / HQ;
    int seg = t2 % NSEG;
    int t3  = t2 / NSEG;
    int w   = t3 % Ww;
    int c   = t3 / Ww;
    int h0  = hq * 4;
    int ch0 = seg * CPG;

    // td flat index: ((c*C + ch)*W + w)*H + h ; h innermost, 16B aligned (H%4==0)
    const float4* __restrict__ base =
        (const float4*)(td + ((size_t)(c * Cc + ch0) * Ww + w) * Hh + h0);
    const int ch_stride4 = (Ww * Hh) / 4;    // 9800 float4 between channels

    float acc0 = 0.f, acc1 = 0.f, acc2 = 0.f, acc3 = 0.f;

    if (work) {
        #pragma unroll 8
        for (int ch = 0; ch < CPG / 2; ++ch) {
            float4 v = __ldg(base + ch * ch_stride4);
            float wv = s_w[ch0 + ch];
            acc0 = fmaf(v.x, wv, acc0);
            acc1 = fmaf(v.y, wv, acc1);
            acc2 = fmaf(v.z, wv, acc2);
            acc3 = fmaf(v.w, wv, acc3);
        }
    }

    // Rendezvous: all 230 prologue blocks are wave-1 and finish in ~2us;
    // by mid-stream (~20us) this is long satisfied.
    if (threadIdx.x == 0) {
        while (*((volatile unsigned*)&g_done) < NBLK_CELL) { __nanosleep(64); }
    }
    __syncthreads();
    __threadfence();   // acquire: table + counts visible

    if (work) {
        // Prefetch; latency hides under the second half of the stream.
        int4 cells = __ldg((const int4*)(g_cell + c * NPTS + w * Hh + h0));
        #pragma unroll 8
        for (int ch = CPG / 2; ch < CPG; ++ch) {
            float4 v = __ldg(base + ch * ch_stride4);
            float wv = s_w[ch0 + ch];
            acc0 = fmaf(v.x, wv, acc0);
            acc1 = fmaf(v.y, wv, acc1);
            acc2 = fmaf(v.z, wv, acc2);
            acc3 = fmaf(v.w, wv, acc3);
        }

        float accs[4] = {acc0, acc1, acc2, acc3};
        int   cls[4]  = {cells.x, cells.y, cells.z, cells.w};
        #pragma unroll
        for (int k = 0; k < 4; ++k) {
            if (cls[k] >= 0)
                atomicAdd(&g_sum[cls[k]], accs[k]);   // partial dot; linear so OK
        }
    }
}

// Consumes the accumulators AND resets all scratch (sum, cnt, g_done).
__global__ void __launch_bounds__(256) final_kernel(float* __restrict__ out,
                                                    const float* __restrict__ bcls) {
    int i = blockIdx.x * blockDim.x + threadIdx.x;
    if (i == 0) g_done = 0;
    if (i >= NCELLS / 2) return;
    float  b = __ldg(bcls);
    float2 s = ((const float2*)g_sum)[i];
    float2 n = ((const float2*)g_cnt)[i];
    float2 o;
    o.x = s.x / fmaxf(n.x, 1.0f) + b;   // cnt==0 -> sum==0 -> b (matches ref)
    o.y = s.y / fmaxf(n.y, 1.0f) + b;
    ((float2*)out)[i] = o;
    float2 z = make_float2(0.f, 0.f);
    ((float2*)g_sum)[i] = z;
    ((float2*)g_cnt)[i] = z;
}

extern "C" void kernel_launch(void* const* d_in, const int* in_sizes, int n_in,
                              void* d_out, int out_size) {
    const float* td   = (const float*)d_in[0];  // (1,6,256,196,200) f32
    const float* cam  = (const float*)d_in[1];  // (1,6,4,4) f32
    const float* lc   = (const float*)d_in[2];  // (4,39200) f32
    const void*  mask = (const void*) d_in[3];  // (200,196) bool-ish
    const float* wcls = (const float*)d_in[4];  // (256,) f32
    const float* bcls = (const float*)d_in[5];  // () f32
    float* out = (float*)d_out;                 // (1,1,400,400) f32

    fused_dot_scatter_kernel<<<NBLK_MAIN, 256>>>(td, cam, lc, mask, wcls);
    final_kernel<<<(NCELLS / 2 + 255) / 256, 256>>>(out, bcls);
}